// round 13
// baseline (speedup 1.0000x reference)
#include <cuda_runtime.h>
#include <cuda_bf16.h>
#include <cuda_fp16.h>
#include <cuda_fp8.h>
#include <math.h>

#define BB   128
#define NTOK 1000
#define NPAD 1024
#define EE   128
#define HH   8
#define NEGV (-1000000000.0f)
#define SCALE 0.25f
#define FP8S 256.0f            // storage scale for e4m3
#define SC_C (0.25f / 256.0f)  // score scale incl. fp8 unscale
#define VSMEM_BYTES (32 * NPAD * 4)   // 128 KB

// K, G: 16-feature interleave (one head / one c-group per uint4 of e4m3):
//   (b,e,n) -> fp8 byte ((b*8 + (e>>4))*NPAD + n)*16 + (e&15)   [8 rows/batch]
// V: 4-feature quads of e4m3: (b,e,n) -> fp8 byte ((b*32 + (e>>2))*NPAD + n)*4 + (e&3)
__device__ uint4    g_K16[BB * 8 * NPAD];
__device__ uint4    g_G16[BB * 8 * NPAD];
__device__ unsigned g_V4u[BB * 32 * NPAD];
__device__ __nv_bfloat16 g_LKp[BB * EE * NPAD];
__device__ float g_SK   [(size_t)BB * NTOK * EE];   // node @ Wstep[128:]
__device__ float g_qbase[BB * EE];
__device__ float g_blk  [BB * NPAD];                // bmlp . LK[:,n]

static __device__ __forceinline__ unsigned char to_fp8(float v) {
    return (unsigned char)__nv_cvt_float_to_fp8(v * FP8S, __NV_SATFINITE, __NV_E4M3);
}

// ---------------------------------------------------------------------------
// Precompute 1: qkv = node @ Wqkv + bqkv -> K16(fp8) / V4u(fp8) / LKp(bf16)
// ---------------------------------------------------------------------------
__global__ void qkv_gemm(const float* __restrict__ node,
                         const float* __restrict__ W,
                         const float* __restrict__ bias) {
    __shared__ float As[16][64];
    __shared__ float Bs[16][64];
    const int b  = blockIdx.z;
    const int n0 = blockIdx.y * 64;
    const int e0 = blockIdx.x * 64;
    const int tx = threadIdx.x, ty = threadIdx.y;
    const int t  = ty * 16 + tx;
    const int an = t >> 2, ak = (t & 3) * 4;
    const int bk = t >> 4, be = (t & 15) * 4;

    float acc[4][4] = {};
    for (int k0 = 0; k0 < 128; k0 += 16) {
        float4 av;
        const int n = n0 + an;
        if (n < NTOK) av = *(const float4*)&node[((size_t)b * NTOK + n) * EE + k0 + ak];
        else          av = make_float4(0.f, 0.f, 0.f, 0.f);
        As[ak + 0][an] = av.x; As[ak + 1][an] = av.y;
        As[ak + 2][an] = av.z; As[ak + 3][an] = av.w;
        *(float4*)&Bs[bk][be] = *(const float4*)&W[(size_t)(k0 + bk) * 384 + e0 + be];
        __syncthreads();
        #pragma unroll
        for (int kk = 0; kk < 16; ++kk) {
            float ar[4], br[4];
            #pragma unroll
            for (int i = 0; i < 4; ++i) ar[i] = As[kk][ty * 4 + i];
            #pragma unroll
            for (int j = 0; j < 4; ++j) br[j] = Bs[kk][tx * 4 + j];
            #pragma unroll
            for (int i = 0; i < 4; ++i)
                #pragma unroll
                for (int j = 0; j < 4; ++j) acc[i][j] += ar[i] * br[j];
        }
        __syncthreads();
    }

    unsigned char* K = (unsigned char*)g_K16;
    unsigned char* V = (unsigned char*)g_V4u;
    #pragma unroll
    for (int i = 0; i < 4; ++i) {
        const int n = n0 + ty * 4 + i;
        if (n >= NTOK) continue;
        #pragma unroll
        for (int j = 0; j < 4; ++j) {
            const int e3 = e0 + tx * 4 + j;
            const float v = acc[i][j] + bias[e3];
            if (e3 < 128) {
                const int e = e3;
                K[((size_t)(b * 8 + (e >> 4)) * NPAD + n) * 16 + (e & 15)] = to_fp8(v);
            } else if (e3 < 256) {
                const int e = e3 - 128;
                V[((size_t)(b * 32 + (e >> 2)) * NPAD + n) * 4 + (e & 3)] = to_fp8(v);
            } else {
                const int e = e3 - 256;
                g_LKp[(size_t)(b * EE + e) * NPAD + n] = __float2bfloat16(v);
            }
        }
    }
}

// ---------------------------------------------------------------------------
// Precompute 2: SK[b][n][e] = node[b,n] @ Wstep[128:256]  (fp32)
// ---------------------------------------------------------------------------
__global__ void sk_gemm(const float* __restrict__ node,
                        const float* __restrict__ Wstep) {
    __shared__ float As[16][64];
    __shared__ float Bs[16][64];
    const float* W2 = Wstep + 128 * EE;
    const int b  = blockIdx.z;
    const int n0 = blockIdx.y * 64;
    const int e0 = blockIdx.x * 64;
    const int tx = threadIdx.x, ty = threadIdx.y;
    const int t  = ty * 16 + tx;
    const int an = t >> 2, ak = (t & 3) * 4;
    const int bk = t >> 4, be = (t & 15) * 4;

    float acc[4][4] = {};
    for (int k0 = 0; k0 < 128; k0 += 16) {
        float4 av;
        const int n = n0 + an;
        if (n < NTOK) av = *(const float4*)&node[((size_t)b * NTOK + n) * EE + k0 + ak];
        else          av = make_float4(0.f, 0.f, 0.f, 0.f);
        As[ak + 0][an] = av.x; As[ak + 1][an] = av.y;
        As[ak + 2][an] = av.z; As[ak + 3][an] = av.w;
        *(float4*)&Bs[bk][be] = *(const float4*)&W2[(size_t)(k0 + bk) * EE + e0 + be];
        __syncthreads();
        #pragma unroll
        for (int kk = 0; kk < 16; ++kk) {
            float ar[4], br[4];
            #pragma unroll
            for (int i = 0; i < 4; ++i) ar[i] = As[kk][ty * 4 + i];
            #pragma unroll
            for (int j = 0; j < 4; ++j) br[j] = Bs[kk][tx * 4 + j];
            #pragma unroll
            for (int i = 0; i < 4; ++i)
                #pragma unroll
                for (int j = 0; j < 4; ++j) acc[i][j] += ar[i] * br[j];
        }
        __syncthreads();
    }
    #pragma unroll
    for (int i = 0; i < 4; ++i) {
        const int n = n0 + ty * 4 + i;
        if (n >= NTOK) continue;
        #pragma unroll
        for (int j = 0; j < 4; ++j)
            g_SK[((size_t)b * NTOK + n) * EE + e0 + tx * 4 + j] = acc[i][j];
    }
}

// ---------------------------------------------------------------------------
// Precompute 3: G[b][c][n] = Wmlp[c][:] . LK[b][:][n]  -> 16-interleaved fp8
// ---------------------------------------------------------------------------
__global__ void g_gemm(const float* __restrict__ Wmlp) {
    __shared__ float As[16][64];   // [e][c]
    __shared__ float Bs[16][64];   // [e][n]
    const int b  = blockIdx.z;
    const int n0 = blockIdx.y * 64;
    const int c0 = blockIdx.x * 64;
    const int tx = threadIdx.x, ty = threadIdx.y;
    const int t  = ty * 16 + tx;
    const int ac = t >> 2, ae = (t & 3) * 4;
    const int bk = t >> 4, bn = (t & 15) * 4;

    float acc[4][4] = {};
    for (int k0 = 0; k0 < 128; k0 += 16) {
        const float4 av = *(const float4*)&Wmlp[(size_t)(c0 + ac) * EE + k0 + ae];
        As[ae + 0][ac] = av.x; As[ae + 1][ac] = av.y;
        As[ae + 2][ac] = av.z; As[ae + 3][ac] = av.w;
        const uint2 r = *(const uint2*)&g_LKp[(size_t)(b * EE + k0 + bk) * NPAD + n0 + bn];
        const float2 v0 = __bfloat1622float2(*(const __nv_bfloat162*)&r.x);
        const float2 v1 = __bfloat1622float2(*(const __nv_bfloat162*)&r.y);
        Bs[bk][bn + 0] = v0.x; Bs[bk][bn + 1] = v0.y;
        Bs[bk][bn + 2] = v1.x; Bs[bk][bn + 3] = v1.y;
        __syncthreads();
        #pragma unroll
        for (int kk = 0; kk < 16; ++kk) {
            float ar[4], br[4];
            #pragma unroll
            for (int i = 0; i < 4; ++i) ar[i] = As[kk][ty * 4 + i];
            #pragma unroll
            for (int j = 0; j < 4; ++j) br[j] = Bs[kk][tx * 4 + j];
            #pragma unroll
            for (int i = 0; i < 4; ++i)
                #pragma unroll
                for (int j = 0; j < 4; ++j) acc[i][j] += ar[i] * br[j];
        }
        __syncthreads();
    }
    unsigned char* G = (unsigned char*)g_G16;
    #pragma unroll
    for (int i = 0; i < 4; ++i) {
        const int c = c0 + ty * 4 + i;
        #pragma unroll
        for (int j = 0; j < 4; ++j) {
            const int n = n0 + tx * 4 + j;
            G[((size_t)(b * 8 + (c >> 4)) * NPAD + n) * 16 + (c & 15)] = to_fp8(acc[i][j]);
        }
    }
}

// ---------------------------------------------------------------------------
// Precompute 4: blk[b][n] = bmlp . LK[b][:][n]
// ---------------------------------------------------------------------------
__global__ void blk_kernel(const float* __restrict__ bmlp) {
    const int b = blockIdx.x, n = threadIdx.x;
    __shared__ float bm[EE];
    if (n < EE) bm[n] = bmlp[n];
    __syncthreads();
    float a = 0.f;
    #pragma unroll 8
    for (int e = 0; e < EE; ++e)
        a += bm[e] * __bfloat162float(g_LKp[(size_t)(b * EE + e) * NPAD + n]);
    g_blk[b * NPAD + n] = a;
}

// ---------------------------------------------------------------------------
// Precompute 5: qbase = graph@Wfix + bfix + bstep + first@Wstep[:128]
// ---------------------------------------------------------------------------
__global__ void qbase_kernel(const float* __restrict__ g,
                             const float* __restrict__ node,
                             const float* __restrict__ Wfix,
                             const float* __restrict__ bfix,
                             const float* __restrict__ Wstep,
                             const float* __restrict__ bstep) {
    const int b = blockIdx.x, e = threadIdx.x;
    __shared__ float gs[EE], fs[EE];
    gs[e] = g[b * EE + e];
    fs[e] = node[(size_t)b * NTOK * EE + e];
    __syncthreads();
    float a = bfix[e] + bstep[e];
    #pragma unroll 4
    for (int k = 0; k < EE; ++k) {
        a += gs[k] * Wfix[(size_t)k * EE + e];
        a += fs[k] * Wstep[(size_t)k * EE + e];
    }
    g_qbase[b * EE + e] = a;
}

__device__ __forceinline__ float tanh_fast(float x) {
    float r;
    asm("tanh.approx.f32 %0, %1;" : "=f"(r) : "f"(x));
    return r;
}

__device__ __forceinline__ __half2 fp8x2_to_h2(unsigned short v) {
    __half2 h;
    asm("cvt.rn.f16x2.e4m3x2 %0, %1;" : "=r"(*(unsigned*)&h) : "h"(v));
    return h;
}

// 16 e4m3 (uint4) dot 16 halves (as 8 x half2), half2 accumulation
__device__ __forceinline__ float dot16_fp8(const uint4 r, const __half2* __restrict__ qh) {
    __half2 acc = __float2half2_rn(0.f);
    acc = __hfma2(fp8x2_to_h2((unsigned short)(r.x)),       qh[0], acc);
    acc = __hfma2(fp8x2_to_h2((unsigned short)(r.x >> 16)), qh[1], acc);
    acc = __hfma2(fp8x2_to_h2((unsigned short)(r.y)),       qh[2], acc);
    acc = __hfma2(fp8x2_to_h2((unsigned short)(r.y >> 16)), qh[3], acc);
    acc = __hfma2(fp8x2_to_h2((unsigned short)(r.z)),       qh[4], acc);
    acc = __hfma2(fp8x2_to_h2((unsigned short)(r.z >> 16)), qh[5], acc);
    acc = __hfma2(fp8x2_to_h2((unsigned short)(r.w)),       qh[6], acc);
    acc = __hfma2(fp8x2_to_h2((unsigned short)(r.w >> 16)), qh[7], acc);
    return __low2float(acc) + __high2float(acc);
}

// ---------------------------------------------------------------------------
// Persistent decode loop; V in smem; C/F work redistributed over idle threads.
// ---------------------------------------------------------------------------
__global__ void __launch_bounds__(1024, 1)
decode_loop(float* __restrict__ out) {
    const int b    = blockIdx.x;
    const int t    = threadIdx.x;
    const int warp = t >> 5, lane = t & 31;

    extern __shared__ unsigned v_s[];                // 32 rows x NPAD fp8-quads (128 KB)

    __shared__ __align__(16) float smp[HH * NPAD];   // 32 KB
    __shared__ float sm_blk[NPAD];                   // 4 KB
    __shared__ int   sm_idx[NPAD];                   // 4 KB
    __shared__ float sm_part[NPAD];                  // 4 KB: F partials
    __shared__ float sm_wred[32 * 9];
    __shared__ int   sm_iwred[32];
    __shared__ __align__(16) __half sm_qh[EE];
    __shared__ __align__(16) __half sm_ctxh[EE];
    __shared__ float sm_qbase[EE];
    __shared__ unsigned char sm_mask[NPAD];
    __shared__ int   sm_cbase[32];
    __shared__ int   sm_newM;

    if (t < EE) sm_qbase[t] = g_qbase[b * EE + t];
    sm_blk[t]  = g_blk[b * NPAD + t];
    sm_idx[t]  = t;
    sm_mask[t] = (t == 0 || t >= NTOK) ? 1 : 0;

    // copy V row for this warp into smem (one-time, 128 KB)
    {
        const uint4* src = (const uint4*)(g_V4u + ((size_t)b * 32 + warp) * NPAD);
        uint4* dst = (uint4*)(v_s + warp * NPAD);
        for (int i = lane; i < NPAD / 4; i += 32) dst[i] = src[i];
    }
    __syncthreads();

    const uint4* kqb = g_K16 + (size_t)b * 8 * NPAD;
    const uint4* gqb = g_G16 + (size_t)b * 8 * NPAD;
    int   cur   = 0;
    float total = 0.f;
    int   M_pad = NPAD;    // active slots (rounded to 32)
    int   nch   = NPAD / 32;
    // work split: s groups of threads each cover all M_pad tokens
    // C has 8 head-chunks (hs = 8/s per group), F has 8 G-chunks (os = 8/s)
    int   s = 1, hs = 8, os = 8;
    int   grp = 0, tok = t;
    bool  active = (t < NPAD);

    #pragma unroll 1
    for (int step = 0; step < NTOK - 1; ++step) {
        // ---- q row (as halves): qbase + SK[cur] ----
        if (t < EE)
            sm_qh[t] = __float2half(sm_qbase[t] + g_SK[((size_t)b * NTOK + cur) * EE + t]);
        __syncthreads();   // S1 (publishes q + mask/compaction from prev iter)

        // ---- C: scores; group grp handles heads [grp*hs, (grp+1)*hs) of token tok ----
        if (active) {
            const uint4* kb = kqb + tok;
            const bool mskT = sm_mask[tok];
            #pragma unroll
            for (int i = 0; i < 8; ++i) {
                if (i >= hs) break;
                const int h = grp * hs + i;
                const float a = dot16_fp8(kb[(size_t)h * NPAD],
                                          (const __half2*)(sm_qh + h * 16));
                smp[h * NPAD + tok] = mskT ? 0.f : __expf(a * SC_C);
            }
        }
        __syncthreads();   // S2

        // ---- D: ctx; warp w owns quad w (e = 4w..4w+3), h = w>>2;
        //      V from smem, 2 tokens per lane, softmax sum folded in ----
        {
            const int h = warp >> 2;
            float a0 = 0.f, a1 = 0.f, a2 = 0.f, a3 = 0.f, ps = 0.f;
            const uint2*  vt2 = (const uint2*)(v_s + warp * NPAD);
            const float2* pp2 = (const float2*)(smp + h * NPAD);
            const int m2 = M_pad >> 1;
            #pragma unroll 4
            for (int n2 = lane; n2 < m2; n2 += 32) {
                const uint2  r  = vt2[n2];          // tokens 2*n2, 2*n2+1
                const float2 p2 = pp2[n2];
                const float2 fA0 = __half22float2(fp8x2_to_h2((unsigned short)r.x));
                const float2 fA1 = __half22float2(fp8x2_to_h2((unsigned short)(r.x >> 16)));
                const float2 fB0 = __half22float2(fp8x2_to_h2((unsigned short)r.y));
                const float2 fB1 = __half22float2(fp8x2_to_h2((unsigned short)(r.y >> 16)));
                ps += p2.x + p2.y;
                a0 += p2.x * fA0.x + p2.y * fB0.x;
                a1 += p2.x * fA0.y + p2.y * fB0.y;
                a2 += p2.x * fA1.x + p2.y * fB1.x;
                a3 += p2.x * fA1.y + p2.y * fB1.y;
            }
            #pragma unroll
            for (int o = 16; o > 0; o >>= 1) {
                a0 += __shfl_xor_sync(~0u, a0, o);
                a1 += __shfl_xor_sync(~0u, a1, o);
                a2 += __shfl_xor_sync(~0u, a2, o);
                a3 += __shfl_xor_sync(~0u, a3, o);
                ps += __shfl_xor_sync(~0u, ps, o);
            }
            if (lane == 0) {
                const float inv = 1.0f / (ps * FP8S);   // undo V fp8 scale
                sm_ctxh[warp * 4 + 0] = __float2half(a0 * inv);
                sm_ctxh[warp * 4 + 1] = __float2half(a1 * inv);
                sm_ctxh[warp * 4 + 2] = __float2half(a2 * inv);
                sm_ctxh[warp * 4 + 3] = __float2half(a3 * inv);
            }
        }
        __syncthreads();   // S3

        // ---- F1: distributed logit partials (8 G-chunks split over groups) ----
        {
            float part = 0.f;
            if (active) {
                const uint4* gb = gqb + tok;
                #pragma unroll
                for (int i = 0; i < 8; ++i) {
                    if (i >= os) break;
                    const int o8 = grp * os + i;
                    part += dot16_fp8(gb[(size_t)o8 * NPAD],
                                      (const __half2*)(sm_ctxh + o8 * 16));
                }
            }
            sm_part[t] = part;
        }
        __syncthreads();   // S4

        // ---- F2: combine partials, argmax + sum exp ----
        {
            float mv = NEGV, sum = 0.f;
            int   mi = t;
            if (t < M_pad) {
                float d = sm_part[t];
                for (int j = 1; j < s; ++j) d += sm_part[t + j * M_pad];
                const float a = sm_blk[t] + d * (1.0f / FP8S);
                if (!sm_mask[t]) {
                    mv  = a;
                    sum = __expf(tanh_fast(a * SCALE) * 10.0f);
                }
            }
            #pragma unroll
            for (int o = 16; o > 0; o >>= 1) {
                const float ov = __shfl_xor_sync(~0u, mv, o);
                const int   oi = __shfl_xor_sync(~0u, mi, o);
                sum += __shfl_xor_sync(~0u, sum, o);
                if (ov > mv || (ov == mv && oi < mi)) { mv = ov; mi = oi; }
            }
            if (lane == 0) {
                sm_wred[warp * 9 + 0] = mv;
                sm_wred[warp * 9 + 1] = sum;
                sm_iwred[warp] = mi;
            }
        }
        __syncthreads();   // S5

        // ---- final reduce, redundant in every warp ----
        {
            float mv = sm_wred[lane * 9 + 0];
            float sum = sm_wred[lane * 9 + 1];
            int   mi = sm_iwred[lane];
            #pragma unroll
            for (int o = 16; o > 0; o >>= 1) {
                const float ov = __shfl_xor_sync(~0u, mv, o);
                const int   oi = __shfl_xor_sync(~0u, mi, o);
                sum += __shfl_xor_sync(~0u, sum, o);
                if (ov > mv || (ov == mv && oi < mi)) { mv = ov; mi = oi; }
            }
            if (t == 0) {
                total += tanhf(mv * SCALE) * 10.0f - logf(sum);  // precise winner
                sm_mask[mi] = 1;
            }
            cur = sm_idx[mi];
        }

        // ---- periodic stable compaction of active tokens ----
        if (((step + 1) & 63) == 0) {
            __syncthreads();                 // CS1
            if (warp == 0) {
                int cnt = 0;
                if (lane < nch) {
                    const unsigned char* mp = sm_mask + lane * 32;
                    #pragma unroll
                    for (int j = 0; j < 32; ++j) cnt += (mp[j] == 0);
                }
                int inc = cnt;
                #pragma unroll
                for (int o = 1; o < 32; o <<= 1) {
                    const int v = __shfl_up_sync(~0u, inc, o);
                    if (lane >= o) inc += v;
                }
                if (lane < nch) sm_cbase[lane] = inc - cnt;
                if (lane == nch - 1) sm_newM = inc;
            }
            __syncthreads();                 // CS2
            {
                // rows 0..7: K16 (uint4, global), 8..15: G16 (uint4, global),
                // rows 16..47: V rows (unsigned, smem)
                for (int rr = warp; rr < 48; rr += 32) {
                    if (rr < 16) {
                        uint4* row = (rr < 8 ? g_K16 + ((size_t)b * 8 + rr) * NPAD
                                             : g_G16 + ((size_t)b * 8 + rr - 8) * NPAD);
                        for (int c = 0; c < nch; ++c) {
                            const int n = c * 32 + lane;
                            const uint4 v = row[n];
                            const bool keep = (sm_mask[n] == 0);
                            const unsigned bal = __ballot_sync(~0u, keep);
                            if (keep)
                                row[sm_cbase[c] + __popc(bal & ((1u << lane) - 1))] = v;
                        }
                    } else {
                        unsigned* row = v_s + (rr - 16) * NPAD;
                        for (int c = 0; c < nch; ++c) {
                            const int n = c * 32 + lane;
                            const unsigned v = row[n];
                            const bool keep = (sm_mask[n] == 0);
                            const unsigned bal = __ballot_sync(~0u, keep);
                            if (keep)
                                row[sm_cbase[c] + __popc(bal & ((1u << lane) - 1))] = v;
                        }
                    }
                }
                if (warp == 0) {
                    for (int c = 0; c < nch; ++c) {
                        const int n = c * 32 + lane;
                        const float v = sm_blk[n];
                        const bool keep = (sm_mask[n] == 0);
                        const unsigned bal = __ballot_sync(~0u, keep);
                        if (keep)
                            sm_blk[sm_cbase[c] + __popc(bal & ((1u << lane) - 1))] = v;
                    }
                }
                if (warp == 1) {
                    for (int c = 0; c < nch; ++c) {
                        const int n = c * 32 + lane;
                        const int v = sm_idx[n];
                        const bool keep = (sm_mask[n] == 0);
                        const unsigned bal = __ballot_sync(~0u, keep);
                        if (keep)
                            sm_idx[sm_cbase[c] + __popc(bal & ((1u << lane) - 1))] = v;
                    }
                }
            }
            __syncthreads();                 // CS3
            const int M = sm_newM;
            M_pad = (M + 31) & ~31;
            nch   = M_pad >> 5;
            sm_mask[t] = (t >= M) ? 1 : 0;
            // recompute work split (8 chunks in both C and F)
            if      (M_pad <= 128) s = 8;
            else if (M_pad <= 256) s = 4;
            else if (M_pad <= 512) s = 2;
            else                   s = 1;
            hs = 8 / s;
            os = 8 / s;
            grp = t / M_pad;
            tok = t - grp * M_pad;
            active = (grp < s);
        }
    }

    if (t == 0) out[b] = total;
}

// ---------------------------------------------------------------------------
extern "C" void kernel_launch(void* const* d_in, const int* in_sizes, int n_in,
                              void* d_out, int out_size) {
    const float* node  = (const float*)d_in[0];
    const float* graph = (const float*)d_in[1];
    const float* Wqkv  = (const float*)d_in[2];
    const float* bqkv  = (const float*)d_in[3];
    const float* Wfix  = (const float*)d_in[4];
    const float* bfix  = (const float*)d_in[5];
    const float* Wstep = (const float*)d_in[6];
    const float* bstep = (const float*)d_in[7];
    const float* Wmlp  = (const float*)d_in[8];
    const float* bmlp  = (const float*)d_in[9];
    float* out = (float*)d_out;

    static int attr_done = 0;
    if (!attr_done) {
        cudaFuncSetAttribute(decode_loop,
                             cudaFuncAttributeMaxDynamicSharedMemorySize, VSMEM_BYTES);
        attr_done = 1;
    }

    dim3 blk2(16, 16);
    qkv_gemm<<<dim3(6, 16, BB), blk2>>>(node, Wqkv, bqkv);
    sk_gemm <<<dim3(2, 16, BB), blk2>>>(node, Wstep);
    g_gemm  <<<dim3(2, 16, BB), blk2>>>(Wmlp);
    blk_kernel <<<BB, NPAD>>>(bmlp);
    qbase_kernel<<<BB, EE>>>(graph, node, Wfix, bfix, Wstep, bstep);
    decode_loop<<<BB, 1024, VSMEM_BYTES>>>(out);
}

// round 14
// speedup vs baseline: 1.1215x; 1.1215x over previous
#include <cuda_runtime.h>
#include <cuda_bf16.h>
#include <cuda_fp16.h>
#include <cuda_fp8.h>
#include <math.h>

#define BB   128
#define NTOK 1000
#define NPAD 1024
#define EE   128
#define HH   8
#define NEGV (-1000000000.0f)
#define SCALE 0.25f
#define FP8S 256.0f            // storage scale for e4m3
#define SC_C (0.25f / 256.0f)  // score scale incl. fp8 unscale
#define VSMEM_BYTES (32 * NPAD * 4)   // 128 KB

// K, G: 16-feature interleave: (b,e,n) -> fp8 byte ((b*8+(e>>4))*NPAD+n)*16+(e&15)
// V: 4-feature quads: (b,e,n) -> fp8 byte ((b*32+(e>>2))*NPAD+n)*4+(e&3)
__device__ uint4    g_K16[BB * 8 * NPAD];
__device__ uint4    g_G16[BB * 8 * NPAD];
__device__ unsigned g_V4u[BB * 32 * NPAD];
__device__ __nv_bfloat16 g_LKp[BB * EE * NPAD];
__device__ float g_SK   [(size_t)BB * NTOK * EE];
__device__ float g_qbase[BB * EE];
__device__ float g_blk  [BB * NPAD];

static __device__ __forceinline__ unsigned char to_fp8(float v) {
    return (unsigned char)__nv_cvt_float_to_fp8(v * FP8S, __NV_SATFINITE, __NV_E4M3);
}

// ---------------------------------------------------------------------------
__global__ void qkv_gemm(const float* __restrict__ node,
                         const float* __restrict__ W,
                         const float* __restrict__ bias) {
    __shared__ float As[16][64];
    __shared__ float Bs[16][64];
    const int b  = blockIdx.z;
    const int n0 = blockIdx.y * 64;
    const int e0 = blockIdx.x * 64;
    const int tx = threadIdx.x, ty = threadIdx.y;
    const int t  = ty * 16 + tx;
    const int an = t >> 2, ak = (t & 3) * 4;
    const int bk = t >> 4, be = (t & 15) * 4;

    float acc[4][4] = {};
    for (int k0 = 0; k0 < 128; k0 += 16) {
        float4 av;
        const int n = n0 + an;
        if (n < NTOK) av = *(const float4*)&node[((size_t)b * NTOK + n) * EE + k0 + ak];
        else          av = make_float4(0.f, 0.f, 0.f, 0.f);
        As[ak + 0][an] = av.x; As[ak + 1][an] = av.y;
        As[ak + 2][an] = av.z; As[ak + 3][an] = av.w;
        *(float4*)&Bs[bk][be] = *(const float4*)&W[(size_t)(k0 + bk) * 384 + e0 + be];
        __syncthreads();
        #pragma unroll
        for (int kk = 0; kk < 16; ++kk) {
            float ar[4], br[4];
            #pragma unroll
            for (int i = 0; i < 4; ++i) ar[i] = As[kk][ty * 4 + i];
            #pragma unroll
            for (int j = 0; j < 4; ++j) br[j] = Bs[kk][tx * 4 + j];
            #pragma unroll
            for (int i = 0; i < 4; ++i)
                #pragma unroll
                for (int j = 0; j < 4; ++j) acc[i][j] += ar[i] * br[j];
        }
        __syncthreads();
    }

    unsigned char* K = (unsigned char*)g_K16;
    unsigned char* V = (unsigned char*)g_V4u;
    #pragma unroll
    for (int i = 0; i < 4; ++i) {
        const int n = n0 + ty * 4 + i;
        if (n >= NTOK) continue;
        #pragma unroll
        for (int j = 0; j < 4; ++j) {
            const int e3 = e0 + tx * 4 + j;
            const float v = acc[i][j] + bias[e3];
            if (e3 < 128) {
                const int e = e3;
                K[((size_t)(b * 8 + (e >> 4)) * NPAD + n) * 16 + (e & 15)] = to_fp8(v);
            } else if (e3 < 256) {
                const int e = e3 - 128;
                V[((size_t)(b * 32 + (e >> 2)) * NPAD + n) * 4 + (e & 3)] = to_fp8(v);
            } else {
                const int e = e3 - 256;
                g_LKp[(size_t)(b * EE + e) * NPAD + n] = __float2bfloat16(v);
            }
        }
    }
}

// ---------------------------------------------------------------------------
__global__ void sk_gemm(const float* __restrict__ node,
                        const float* __restrict__ Wstep) {
    __shared__ float As[16][64];
    __shared__ float Bs[16][64];
    const float* W2 = Wstep + 128 * EE;
    const int b  = blockIdx.z;
    const int n0 = blockIdx.y * 64;
    const int e0 = blockIdx.x * 64;
    const int tx = threadIdx.x, ty = threadIdx.y;
    const int t  = ty * 16 + tx;
    const int an = t >> 2, ak = (t & 3) * 4;
    const int bk = t >> 4, be = (t & 15) * 4;

    float acc[4][4] = {};
    for (int k0 = 0; k0 < 128; k0 += 16) {
        float4 av;
        const int n = n0 + an;
        if (n < NTOK) av = *(const float4*)&node[((size_t)b * NTOK + n) * EE + k0 + ak];
        else          av = make_float4(0.f, 0.f, 0.f, 0.f);
        As[ak + 0][an] = av.x; As[ak + 1][an] = av.y;
        As[ak + 2][an] = av.z; As[ak + 3][an] = av.w;
        *(float4*)&Bs[bk][be] = *(const float4*)&W2[(size_t)(k0 + bk) * EE + e0 + be];
        __syncthreads();
        #pragma unroll
        for (int kk = 0; kk < 16; ++kk) {
            float ar[4], br[4];
            #pragma unroll
            for (int i = 0; i < 4; ++i) ar[i] = As[kk][ty * 4 + i];
            #pragma unroll
            for (int j = 0; j < 4; ++j) br[j] = Bs[kk][tx * 4 + j];
            #pragma unroll
            for (int i = 0; i < 4; ++i)
                #pragma unroll
                for (int j = 0; j < 4; ++j) acc[i][j] += ar[i] * br[j];
        }
        __syncthreads();
    }
    #pragma unroll
    for (int i = 0; i < 4; ++i) {
        const int n = n0 + ty * 4 + i;
        if (n >= NTOK) continue;
        #pragma unroll
        for (int j = 0; j < 4; ++j)
            g_SK[((size_t)b * NTOK + n) * EE + e0 + tx * 4 + j] = acc[i][j];
    }
}

// ---------------------------------------------------------------------------
__global__ void g_gemm(const float* __restrict__ Wmlp) {
    __shared__ float As[16][64];
    __shared__ float Bs[16][64];
    const int b  = blockIdx.z;
    const int n0 = blockIdx.y * 64;
    const int c0 = blockIdx.x * 64;
    const int tx = threadIdx.x, ty = threadIdx.y;
    const int t  = ty * 16 + tx;
    const int ac = t >> 2, ae = (t & 3) * 4;
    const int bk = t >> 4, bn = (t & 15) * 4;

    float acc[4][4] = {};
    for (int k0 = 0; k0 < 128; k0 += 16) {
        const float4 av = *(const float4*)&Wmlp[(size_t)(c0 + ac) * EE + k0 + ae];
        As[ae + 0][ac] = av.x; As[ae + 1][ac] = av.y;
        As[ae + 2][ac] = av.z; As[ae + 3][ac] = av.w;
        const uint2 r = *(const uint2*)&g_LKp[(size_t)(b * EE + k0 + bk) * NPAD + n0 + bn];
        const float2 v0 = __bfloat1622float2(*(const __nv_bfloat162*)&r.x);
        const float2 v1 = __bfloat1622float2(*(const __nv_bfloat162*)&r.y);
        Bs[bk][bn + 0] = v0.x; Bs[bk][bn + 1] = v0.y;
        Bs[bk][bn + 2] = v1.x; Bs[bk][bn + 3] = v1.y;
        __syncthreads();
        #pragma unroll
        for (int kk = 0; kk < 16; ++kk) {
            float ar[4], br[4];
            #pragma unroll
            for (int i = 0; i < 4; ++i) ar[i] = As[kk][ty * 4 + i];
            #pragma unroll
            for (int j = 0; j < 4; ++j) br[j] = Bs[kk][tx * 4 + j];
            #pragma unroll
            for (int i = 0; i < 4; ++i)
                #pragma unroll
                for (int j = 0; j < 4; ++j) acc[i][j] += ar[i] * br[j];
        }
        __syncthreads();
    }
    unsigned char* G = (unsigned char*)g_G16;
    #pragma unroll
    for (int i = 0; i < 4; ++i) {
        const int c = c0 + ty * 4 + i;
        #pragma unroll
        for (int j = 0; j < 4; ++j) {
            const int n = n0 + tx * 4 + j;
            G[((size_t)(b * 8 + (c >> 4)) * NPAD + n) * 16 + (c & 15)] = to_fp8(acc[i][j]);
        }
    }
}

// ---------------------------------------------------------------------------
__global__ void blk_kernel(const float* __restrict__ bmlp) {
    const int b = blockIdx.x, n = threadIdx.x;
    __shared__ float bm[EE];
    if (n < EE) bm[n] = bmlp[n];
    __syncthreads();
    float a = 0.f;
    #pragma unroll 8
    for (int e = 0; e < EE; ++e)
        a += bm[e] * __bfloat162float(g_LKp[(size_t)(b * EE + e) * NPAD + n]);
    g_blk[b * NPAD + n] = a;
}

// ---------------------------------------------------------------------------
__global__ void qbase_kernel(const float* __restrict__ g,
                             const float* __restrict__ node,
                             const float* __restrict__ Wfix,
                             const float* __restrict__ bfix,
                             const float* __restrict__ Wstep,
                             const float* __restrict__ bstep) {
    const int b = blockIdx.x, e = threadIdx.x;
    __shared__ float gs[EE], fs[EE];
    gs[e] = g[b * EE + e];
    fs[e] = node[(size_t)b * NTOK * EE + e];
    __syncthreads();
    float a = bfix[e] + bstep[e];
    #pragma unroll 4
    for (int k = 0; k < EE; ++k) {
        a += gs[k] * Wfix[(size_t)k * EE + e];
        a += fs[k] * Wstep[(size_t)k * EE + e];
    }
    g_qbase[b * EE + e] = a;
}

__device__ __forceinline__ float tanh_fast(float x) {
    float r;
    asm("tanh.approx.f32 %0, %1;" : "=f"(r) : "f"(x));
    return r;
}

__device__ __forceinline__ __half2 fp8x2_to_h2(unsigned short v) {
    __half2 h;
    asm("cvt.rn.f16x2.e4m3x2 %0, %1;" : "=r"(*(unsigned*)&h) : "h"(v));
    return h;
}

__device__ __forceinline__ float dot16_fp8(const uint4 r, const __half2* __restrict__ qh) {
    __half2 acc = __float2half2_rn(0.f);
    acc = __hfma2(fp8x2_to_h2((unsigned short)(r.x)),       qh[0], acc);
    acc = __hfma2(fp8x2_to_h2((unsigned short)(r.x >> 16)), qh[1], acc);
    acc = __hfma2(fp8x2_to_h2((unsigned short)(r.y)),       qh[2], acc);
    acc = __hfma2(fp8x2_to_h2((unsigned short)(r.y >> 16)), qh[3], acc);
    acc = __hfma2(fp8x2_to_h2((unsigned short)(r.z)),       qh[4], acc);
    acc = __hfma2(fp8x2_to_h2((unsigned short)(r.z >> 16)), qh[5], acc);
    acc = __hfma2(fp8x2_to_h2((unsigned short)(r.w)),       qh[6], acc);
    acc = __hfma2(fp8x2_to_h2((unsigned short)(r.w >> 16)), qh[7], acc);
    return __low2float(acc) + __high2float(acc);
}

// ---------------------------------------------------------------------------
// Persistent decode loop; V in smem; uniform-branch work split (s=1 path == R10).
// ---------------------------------------------------------------------------
__global__ void __launch_bounds__(1024, 1)
decode_loop(float* __restrict__ out) {
    const int b    = blockIdx.x;
    const int t    = threadIdx.x;
    const int warp = t >> 5, lane = t & 31;

    extern __shared__ unsigned v_s[];                // 128 KB V

    __shared__ __align__(16) float smp[HH * NPAD];
    __shared__ float sm_blk[NPAD];
    __shared__ int   sm_idx[NPAD];
    __shared__ float sm_part[NPAD];
    __shared__ float sm_wred[32 * 9];
    __shared__ int   sm_iwred[32];
    __shared__ __align__(16) __half sm_qh[EE];
    __shared__ __align__(16) __half sm_ctxh[EE];
    __shared__ float sm_qbase[EE];
    __shared__ unsigned char sm_mask[NPAD];
    __shared__ int   sm_cbase[32];
    __shared__ int   sm_newM;

    if (t < EE) sm_qbase[t] = g_qbase[b * EE + t];
    sm_blk[t]  = g_blk[b * NPAD + t];
    sm_idx[t]  = t;
    sm_mask[t] = (t == 0 || t >= NTOK) ? 1 : 0;

    {
        const uint4* src = (const uint4*)(g_V4u + ((size_t)b * 32 + warp) * NPAD);
        uint4* dst = (uint4*)(v_s + warp * NPAD);
        for (int i = lane; i < NPAD / 4; i += 32) dst[i] = src[i];
    }
    __syncthreads();

    const uint4* kqb = g_K16 + (size_t)b * 8 * NPAD;
    const uint4* gqb = g_G16 + (size_t)b * 8 * NPAD;
    const uint4* kq  = kqb + t;    // s==1 fast path pointers (tok == t)
    const uint4* gq  = gqb + t;
    int   cur   = 0;
    float total = 0.f;
    int   M_pad = NPAD;
    int   nch   = NPAD / 32;
    int   s = 1;                    // block-uniform split factor
    int   grp = 0, tok = t;
    bool  active = true;

    #pragma unroll 1
    for (int step = 0; step < NTOK - 1; ++step) {
        // ---- q row (as halves) ----
        if (t < EE)
            sm_qh[t] = __float2half(sm_qbase[t] + g_SK[((size_t)b * NTOK + cur) * EE + t]);
        __syncthreads();   // S1

        // ---- C: scores ----
        if (s == 1) {
            if (t < M_pad) {
                const bool msk = sm_mask[t];
                #pragma unroll
                for (int h = 0; h < HH; ++h) {
                    const float a = dot16_fp8(kq[(size_t)h * NPAD],
                                              (const __half2*)(sm_qh + h * 16));
                    smp[h * NPAD + t] = msk ? 0.f : __expf(a * SC_C);
                }
            }
        } else if (active) {
            const uint4* kb = kqb + tok;
            const bool mskT = sm_mask[tok];
            if (s == 2) {
                #pragma unroll
                for (int i = 0; i < 4; ++i) {
                    const int h = grp * 4 + i;
                    const float a = dot16_fp8(kb[(size_t)h * NPAD],
                                              (const __half2*)(sm_qh + h * 16));
                    smp[h * NPAD + tok] = mskT ? 0.f : __expf(a * SC_C);
                }
            } else if (s == 4) {
                #pragma unroll
                for (int i = 0; i < 2; ++i) {
                    const int h = grp * 2 + i;
                    const float a = dot16_fp8(kb[(size_t)h * NPAD],
                                              (const __half2*)(sm_qh + h * 16));
                    smp[h * NPAD + tok] = mskT ? 0.f : __expf(a * SC_C);
                }
            } else {
                const int h = grp;
                const float a = dot16_fp8(kb[(size_t)h * NPAD],
                                          (const __half2*)(sm_qh + h * 16));
                smp[h * NPAD + tok] = mskT ? 0.f : __expf(a * SC_C);
            }
        }
        __syncthreads();   // S2

        // ---- D: ctx; warp w owns quad w; V in smem, 2 tokens/lane ----
        {
            const int h = warp >> 2;
            float a0 = 0.f, a1 = 0.f, a2 = 0.f, a3 = 0.f, ps = 0.f;
            const uint2*  vt2 = (const uint2*)(v_s + warp * NPAD);
            const float2* pp2 = (const float2*)(smp + h * NPAD);
            const int m2 = M_pad >> 1;
            #pragma unroll 4
            for (int n2 = lane; n2 < m2; n2 += 32) {
                const uint2  r  = vt2[n2];
                const float2 p2 = pp2[n2];
                const float2 fA0 = __half22float2(fp8x2_to_h2((unsigned short)r.x));
                const float2 fA1 = __half22float2(fp8x2_to_h2((unsigned short)(r.x >> 16)));
                const float2 fB0 = __half22float2(fp8x2_to_h2((unsigned short)r.y));
                const float2 fB1 = __half22float2(fp8x2_to_h2((unsigned short)(r.y >> 16)));
                ps += p2.x + p2.y;
                a0 += p2.x * fA0.x + p2.y * fB0.x;
                a1 += p2.x * fA0.y + p2.y * fB0.y;
                a2 += p2.x * fA1.x + p2.y * fB1.x;
                a3 += p2.x * fA1.y + p2.y * fB1.y;
            }
            #pragma unroll
            for (int o = 16; o > 0; o >>= 1) {
                a0 += __shfl_xor_sync(~0u, a0, o);
                a1 += __shfl_xor_sync(~0u, a1, o);
                a2 += __shfl_xor_sync(~0u, a2, o);
                a3 += __shfl_xor_sync(~0u, a3, o);
                ps += __shfl_xor_sync(~0u, ps, o);
            }
            if (lane == 0) {
                const float inv = 1.0f / (ps * FP8S);
                sm_ctxh[warp * 4 + 0] = __float2half(a0 * inv);
                sm_ctxh[warp * 4 + 1] = __float2half(a1 * inv);
                sm_ctxh[warp * 4 + 2] = __float2half(a2 * inv);
                sm_ctxh[warp * 4 + 3] = __float2half(a3 * inv);
            }
        }
        __syncthreads();   // S3

        // ---- F: logits; s==1 fully fused, s>1 via sm_part (uniform branch) ----
        float dfull = 0.f;
        if (s == 1) {
            if (t < M_pad) {
                #pragma unroll
                for (int o8 = 0; o8 < 8; ++o8)
                    dfull += dot16_fp8(gq[(size_t)o8 * NPAD],
                                       (const __half2*)(sm_ctxh + o8 * 16));
            }
        } else {
            float part = 0.f;
            if (active) {
                const uint4* gb = gqb + tok;
                if (s == 2) {
                    #pragma unroll
                    for (int i = 0; i < 4; ++i) {
                        const int o8 = grp * 4 + i;
                        part += dot16_fp8(gb[(size_t)o8 * NPAD],
                                          (const __half2*)(sm_ctxh + o8 * 16));
                    }
                } else if (s == 4) {
                    #pragma unroll
                    for (int i = 0; i < 2; ++i) {
                        const int o8 = grp * 2 + i;
                        part += dot16_fp8(gb[(size_t)o8 * NPAD],
                                          (const __half2*)(sm_ctxh + o8 * 16));
                    }
                } else {
                    part = dot16_fp8(gb[(size_t)grp * NPAD],
                                     (const __half2*)(sm_ctxh + grp * 16));
                }
            }
            sm_part[t] = part;
            __syncthreads();               // SF (uniform: only when s > 1)
            if (t < M_pad) {
                dfull = sm_part[t];
                for (int j = 1; j < s; ++j) dfull += sm_part[t + j * M_pad];
            }
        }
        {
            float mv = NEGV, sum = 0.f;
            int   mi = t;
            if (t < M_pad) {
                const float a = sm_blk[t] + dfull * (1.0f / FP8S);
                if (!sm_mask[t]) {
                    mv  = a;
                    sum = __expf(tanh_fast(a * SCALE) * 10.0f);
                }
            }
            #pragma unroll
            for (int o = 16; o > 0; o >>= 1) {
                const float ov = __shfl_xor_sync(~0u, mv, o);
                const int   oi = __shfl_xor_sync(~0u, mi, o);
                sum += __shfl_xor_sync(~0u, sum, o);
                if (ov > mv || (ov == mv && oi < mi)) { mv = ov; mi = oi; }
            }
            if (lane == 0) {
                sm_wred[warp * 9 + 0] = mv;
                sm_wred[warp * 9 + 1] = sum;
                sm_iwred[warp] = mi;
            }
        }
        __syncthreads();   // S4

        // ---- final reduce, redundant in every warp ----
        {
            float mv = sm_wred[lane * 9 + 0];
            float sum = sm_wred[lane * 9 + 1];
            int   mi = sm_iwred[lane];
            #pragma unroll
            for (int o = 16; o > 0; o >>= 1) {
                const float ov = __shfl_xor_sync(~0u, mv, o);
                const int   oi = __shfl_xor_sync(~0u, mi, o);
                sum += __shfl_xor_sync(~0u, sum, o);
                if (ov > mv || (ov == mv && oi < mi)) { mv = ov; mi = oi; }
            }
            if (t == 0) {
                total += tanhf(mv * SCALE) * 10.0f - logf(sum);
                sm_mask[mi] = 1;
            }
            cur = sm_idx[mi];
        }

        // ---- periodic stable compaction ----
        if (((step + 1) & 63) == 0) {
            __syncthreads();                 // CS1
            if (warp == 0) {
                int cnt = 0;
                if (lane < nch) {
                    const unsigned char* mp = sm_mask + lane * 32;
                    #pragma unroll
                    for (int j = 0; j < 32; ++j) cnt += (mp[j] == 0);
                }
                int inc = cnt;
                #pragma unroll
                for (int o = 1; o < 32; o <<= 1) {
                    const int v = __shfl_up_sync(~0u, inc, o);
                    if (lane >= o) inc += v;
                }
                if (lane < nch) sm_cbase[lane] = inc - cnt;
                if (lane == nch - 1) sm_newM = inc;
            }
            __syncthreads();                 // CS2
            {
                for (int rr = warp; rr < 48; rr += 32) {
                    if (rr < 16) {
                        uint4* row = (rr < 8 ? g_K16 + ((size_t)b * 8 + rr) * NPAD
                                             : g_G16 + ((size_t)b * 8 + rr - 8) * NPAD);
                        for (int c = 0; c < nch; ++c) {
                            const int n = c * 32 + lane;
                            const uint4 v = row[n];
                            const bool keep = (sm_mask[n] == 0);
                            const unsigned bal = __ballot_sync(~0u, keep);
                            if (keep)
                                row[sm_cbase[c] + __popc(bal & ((1u << lane) - 1))] = v;
                        }
                    } else {
                        unsigned* row = v_s + (rr - 16) * NPAD;
                        for (int c = 0; c < nch; ++c) {
                            const int n = c * 32 + lane;
                            const unsigned v = row[n];
                            const bool keep = (sm_mask[n] == 0);
                            const unsigned bal = __ballot_sync(~0u, keep);
                            if (keep)
                                row[sm_cbase[c] + __popc(bal & ((1u << lane) - 1))] = v;
                        }
                    }
                }
                if (warp == 0) {
                    for (int c = 0; c < nch; ++c) {
                        const int n = c * 32 + lane;
                        const float v = sm_blk[n];
                        const bool keep = (sm_mask[n] == 0);
                        const unsigned bal = __ballot_sync(~0u, keep);
                        if (keep)
                            sm_blk[sm_cbase[c] + __popc(bal & ((1u << lane) - 1))] = v;
                    }
                }
                if (warp == 1) {
                    for (int c = 0; c < nch; ++c) {
                        const int n = c * 32 + lane;
                        const int v = sm_idx[n];
                        const bool keep = (sm_mask[n] == 0);
                        const unsigned bal = __ballot_sync(~0u, keep);
                        if (keep)
                            sm_idx[sm_cbase[c] + __popc(bal & ((1u << lane) - 1))] = v;
                    }
                }
            }
            __syncthreads();                 // CS3
            const int M = sm_newM;
            M_pad = (M + 31) & ~31;
            nch   = M_pad >> 5;
            sm_mask[t] = (t >= M) ? 1 : 0;
            if      (M_pad <= 128) s = 8;
            else if (M_pad <= 256) s = 4;
            else if (M_pad <= 512) s = 2;
            else                   s = 1;
            grp = t / M_pad;
            tok = t - grp * M_pad;
            active = (grp < s);
        }
    }

    if (t == 0) out[b] = total;
}

// ---------------------------------------------------------------------------
extern "C" void kernel_launch(void* const* d_in, const int* in_sizes, int n_in,
                              void* d_out, int out_size) {
    const float* node  = (const float*)d_in[0];
    const float* graph = (const float*)d_in[1];
    const float* Wqkv  = (const float*)d_in[2];
    const float* bqkv  = (const float*)d_in[3];
    const float* Wfix  = (const float*)d_in[4];
    const float* bfix  = (const float*)d_in[5];
    const float* Wstep = (const float*)d_in[6];
    const float* bstep = (const float*)d_in[7];
    const float* Wmlp  = (const float*)d_in[8];
    const float* bmlp  = (const float*)d_in[9];
    float* out = (float*)d_out;

    static int attr_done = 0;
    if (!attr_done) {
        cudaFuncSetAttribute(decode_loop,
                             cudaFuncAttributeMaxDynamicSharedMemorySize, VSMEM_BYTES);
        attr_done = 1;
    }

    dim3 blk2(16, 16);
    qkv_gemm<<<dim3(6, 16, BB), blk2>>>(node, Wqkv, bqkv);
    sk_gemm <<<dim3(2, 16, BB), blk2>>>(node, Wstep);
    g_gemm  <<<dim3(2, 16, BB), blk2>>>(Wmlp);
    blk_kernel <<<BB, NPAD>>>(bmlp);
    qbase_kernel<<<BB, EE>>>(graph, node, Wfix, bfix, Wstep, bstep);
    decode_loop<<<BB, 1024, VSMEM_BYTES>>>(out);
}

// round 15
// speedup vs baseline: 1.2031x; 1.0728x over previous
#include <cuda_runtime.h>
#include <cuda_bf16.h>
#include <cuda_fp16.h>
#include <cuda_fp8.h>
#include <math.h>

#define BB   128
#define NTOK 1000
#define NPAD 1024
#define EE   128
#define HH   8
#define NEGV (-1000000000.0f)
#define SCALE 0.25f
#define FP8S 256.0f            // storage scale for e4m3
#define SC_C (0.25f / 256.0f)  // score scale incl. fp8 unscale
#define VSMEM_BYTES (32 * NPAD * 4)   // 128 KB

// K, G: 16-feature interleave: (b,e,n) -> fp8 byte ((b*8+(e>>4))*NPAD+n)*16+(e&15)
// V: 4-feature quads: (b,e,n) -> fp8 byte ((b*32+(e>>2))*NPAD+n)*4+(e&3)
__device__ uint4    g_K16[BB * 8 * NPAD];
__device__ uint4    g_G16[BB * 8 * NPAD];
__device__ unsigned g_V4u[BB * 32 * NPAD];
__device__ __nv_bfloat16 g_LKp[BB * EE * NPAD];
__device__ float g_SK   [(size_t)BB * NTOK * EE];
__device__ float g_qbase[BB * EE];
__device__ float g_blk  [BB * NPAD];

static __device__ __forceinline__ unsigned char to_fp8(float v) {
    return (unsigned char)__nv_cvt_float_to_fp8(v * FP8S, __NV_SATFINITE, __NV_E4M3);
}

// ---------------------------------------------------------------------------
__global__ void qkv_gemm(const float* __restrict__ node,
                         const float* __restrict__ W,
                         const float* __restrict__ bias) {
    __shared__ float As[16][64];
    __shared__ float Bs[16][64];
    const int b  = blockIdx.z;
    const int n0 = blockIdx.y * 64;
    const int e0 = blockIdx.x * 64;
    const int tx = threadIdx.x, ty = threadIdx.y;
    const int t  = ty * 16 + tx;
    const int an = t >> 2, ak = (t & 3) * 4;
    const int bk = t >> 4, be = (t & 15) * 4;

    float acc[4][4] = {};
    for (int k0 = 0; k0 < 128; k0 += 16) {
        float4 av;
        const int n = n0 + an;
        if (n < NTOK) av = *(const float4*)&node[((size_t)b * NTOK + n) * EE + k0 + ak];
        else          av = make_float4(0.f, 0.f, 0.f, 0.f);
        As[ak + 0][an] = av.x; As[ak + 1][an] = av.y;
        As[ak + 2][an] = av.z; As[ak + 3][an] = av.w;
        *(float4*)&Bs[bk][be] = *(const float4*)&W[(size_t)(k0 + bk) * 384 + e0 + be];
        __syncthreads();
        #pragma unroll
        for (int kk = 0; kk < 16; ++kk) {
            float ar[4], br[4];
            #pragma unroll
            for (int i = 0; i < 4; ++i) ar[i] = As[kk][ty * 4 + i];
            #pragma unroll
            for (int j = 0; j < 4; ++j) br[j] = Bs[kk][tx * 4 + j];
            #pragma unroll
            for (int i = 0; i < 4; ++i)
                #pragma unroll
                for (int j = 0; j < 4; ++j) acc[i][j] += ar[i] * br[j];
        }
        __syncthreads();
    }

    unsigned char* K = (unsigned char*)g_K16;
    unsigned char* V = (unsigned char*)g_V4u;
    #pragma unroll
    for (int i = 0; i < 4; ++i) {
        const int n = n0 + ty * 4 + i;
        if (n >= NTOK) continue;
        #pragma unroll
        for (int j = 0; j < 4; ++j) {
            const int e3 = e0 + tx * 4 + j;
            const float v = acc[i][j] + bias[e3];
            if (e3 < 128) {
                const int e = e3;
                K[((size_t)(b * 8 + (e >> 4)) * NPAD + n) * 16 + (e & 15)] = to_fp8(v);
            } else if (e3 < 256) {
                const int e = e3 - 128;
                V[((size_t)(b * 32 + (e >> 2)) * NPAD + n) * 4 + (e & 3)] = to_fp8(v);
            } else {
                const int e = e3 - 256;
                g_LKp[(size_t)(b * EE + e) * NPAD + n] = __float2bfloat16(v);
            }
        }
    }
}

// ---------------------------------------------------------------------------
__global__ void sk_gemm(const float* __restrict__ node,
                        const float* __restrict__ Wstep) {
    __shared__ float As[16][64];
    __shared__ float Bs[16][64];
    const float* W2 = Wstep + 128 * EE;
    const int b  = blockIdx.z;
    const int n0 = blockIdx.y * 64;
    const int e0 = blockIdx.x * 64;
    const int tx = threadIdx.x, ty = threadIdx.y;
    const int t  = ty * 16 + tx;
    const int an = t >> 2, ak = (t & 3) * 4;
    const int bk = t >> 4, be = (t & 15) * 4;

    float acc[4][4] = {};
    for (int k0 = 0; k0 < 128; k0 += 16) {
        float4 av;
        const int n = n0 + an;
        if (n < NTOK) av = *(const float4*)&node[((size_t)b * NTOK + n) * EE + k0 + ak];
        else          av = make_float4(0.f, 0.f, 0.f, 0.f);
        As[ak + 0][an] = av.x; As[ak + 1][an] = av.y;
        As[ak + 2][an] = av.z; As[ak + 3][an] = av.w;
        *(float4*)&Bs[bk][be] = *(const float4*)&W2[(size_t)(k0 + bk) * EE + e0 + be];
        __syncthreads();
        #pragma unroll
        for (int kk = 0; kk < 16; ++kk) {
            float ar[4], br[4];
            #pragma unroll
            for (int i = 0; i < 4; ++i) ar[i] = As[kk][ty * 4 + i];
            #pragma unroll
            for (int j = 0; j < 4; ++j) br[j] = Bs[kk][tx * 4 + j];
            #pragma unroll
            for (int i = 0; i < 4; ++i)
                #pragma unroll
                for (int j = 0; j < 4; ++j) acc[i][j] += ar[i] * br[j];
        }
        __syncthreads();
    }
    #pragma unroll
    for (int i = 0; i < 4; ++i) {
        const int n = n0 + ty * 4 + i;
        if (n >= NTOK) continue;
        #pragma unroll
        for (int j = 0; j < 4; ++j)
            g_SK[((size_t)b * NTOK + n) * EE + e0 + tx * 4 + j] = acc[i][j];
    }
}

// ---------------------------------------------------------------------------
__global__ void g_gemm(const float* __restrict__ Wmlp) {
    __shared__ float As[16][64];
    __shared__ float Bs[16][64];
    const int b  = blockIdx.z;
    const int n0 = blockIdx.y * 64;
    const int c0 = blockIdx.x * 64;
    const int tx = threadIdx.x, ty = threadIdx.y;
    const int t  = ty * 16 + tx;
    const int ac = t >> 2, ae = (t & 3) * 4;
    const int bk = t >> 4, bn = (t & 15) * 4;

    float acc[4][4] = {};
    for (int k0 = 0; k0 < 128; k0 += 16) {
        const float4 av = *(const float4*)&Wmlp[(size_t)(c0 + ac) * EE + k0 + ae];
        As[ae + 0][ac] = av.x; As[ae + 1][ac] = av.y;
        As[ae + 2][ac] = av.z; As[ae + 3][ac] = av.w;
        const uint2 r = *(const uint2*)&g_LKp[(size_t)(b * EE + k0 + bk) * NPAD + n0 + bn];
        const float2 v0 = __bfloat1622float2(*(const __nv_bfloat162*)&r.x);
        const float2 v1 = __bfloat1622float2(*(const __nv_bfloat162*)&r.y);
        Bs[bk][bn + 0] = v0.x; Bs[bk][bn + 1] = v0.y;
        Bs[bk][bn + 2] = v1.x; Bs[bk][bn + 3] = v1.y;
        __syncthreads();
        #pragma unroll
        for (int kk = 0; kk < 16; ++kk) {
            float ar[4], br[4];
            #pragma unroll
            for (int i = 0; i < 4; ++i) ar[i] = As[kk][ty * 4 + i];
            #pragma unroll
            for (int j = 0; j < 4; ++j) br[j] = Bs[kk][tx * 4 + j];
            #pragma unroll
            for (int i = 0; i < 4; ++i)
                #pragma unroll
                for (int j = 0; j < 4; ++j) acc[i][j] += ar[i] * br[j];
        }
        __syncthreads();
    }
    unsigned char* G = (unsigned char*)g_G16;
    #pragma unroll
    for (int i = 0; i < 4; ++i) {
        const int c = c0 + ty * 4 + i;
        #pragma unroll
        for (int j = 0; j < 4; ++j) {
            const int n = n0 + tx * 4 + j;
            G[((size_t)(b * 8 + (c >> 4)) * NPAD + n) * 16 + (c & 15)] = to_fp8(acc[i][j]);
        }
    }
}

// ---------------------------------------------------------------------------
__global__ void blk_kernel(const float* __restrict__ bmlp) {
    const int b = blockIdx.x, n = threadIdx.x;
    __shared__ float bm[EE];
    if (n < EE) bm[n] = bmlp[n];
    __syncthreads();
    float a = 0.f;
    #pragma unroll 8
    for (int e = 0; e < EE; ++e)
        a += bm[e] * __bfloat162float(g_LKp[(size_t)(b * EE + e) * NPAD + n]);
    g_blk[b * NPAD + n] = a;
}

// ---------------------------------------------------------------------------
__global__ void qbase_kernel(const float* __restrict__ g,
                             const float* __restrict__ node,
                             const float* __restrict__ Wfix,
                             const float* __restrict__ bfix,
                             const float* __restrict__ Wstep,
                             const float* __restrict__ bstep) {
    const int b = blockIdx.x, e = threadIdx.x;
    __shared__ float gs[EE], fs[EE];
    gs[e] = g[b * EE + e];
    fs[e] = node[(size_t)b * NTOK * EE + e];
    __syncthreads();
    float a = bfix[e] + bstep[e];
    #pragma unroll 4
    for (int k = 0; k < EE; ++k) {
        a += gs[k] * Wfix[(size_t)k * EE + e];
        a += fs[k] * Wstep[(size_t)k * EE + e];
    }
    g_qbase[b * EE + e] = a;
}

__device__ __forceinline__ float tanh_fast(float x) {
    float r;
    asm("tanh.approx.f32 %0, %1;" : "=f"(r) : "f"(x));
    return r;
}

__device__ __forceinline__ __half2 fp8x2_to_h2(unsigned short v) {
    __half2 h;
    asm("cvt.rn.f16x2.e4m3x2 %0, %1;" : "=r"(*(unsigned*)&h) : "h"(v));
    return h;
}

__device__ __forceinline__ float dot16_fp8(const uint4 r, const __half2* __restrict__ qh) {
    __half2 acc = __float2half2_rn(0.f);
    acc = __hfma2(fp8x2_to_h2((unsigned short)(r.x)),       qh[0], acc);
    acc = __hfma2(fp8x2_to_h2((unsigned short)(r.x >> 16)), qh[1], acc);
    acc = __hfma2(fp8x2_to_h2((unsigned short)(r.y)),       qh[2], acc);
    acc = __hfma2(fp8x2_to_h2((unsigned short)(r.y >> 16)), qh[3], acc);
    acc = __hfma2(fp8x2_to_h2((unsigned short)(r.z)),       qh[4], acc);
    acc = __hfma2(fp8x2_to_h2((unsigned short)(r.z >> 16)), qh[5], acc);
    acc = __hfma2(fp8x2_to_h2((unsigned short)(r.w)),       qh[6], acc);
    acc = __hfma2(fp8x2_to_h2((unsigned short)(r.w >> 16)), qh[7], acc);
    return __low2float(acc) + __high2float(acc);
}

// ---------------------------------------------------------------------------
// Persistent decode loop (R10 structure); C/F loads batched 4-at-a-time.
// ---------------------------------------------------------------------------
__global__ void __launch_bounds__(1024, 1)
decode_loop(float* __restrict__ out) {
    const int b    = blockIdx.x;
    const int t    = threadIdx.x;
    const int warp = t >> 5, lane = t & 31;

    extern __shared__ unsigned v_s[];                // 128 KB V

    __shared__ __align__(16) float smp[HH * NPAD];
    __shared__ float sm_blk[NPAD];
    __shared__ int   sm_idx[NPAD];
    __shared__ float sm_wred[32 * 9];
    __shared__ int   sm_iwred[32];
    __shared__ __align__(16) __half sm_qh[EE];
    __shared__ __align__(16) __half sm_ctxh[EE];
    __shared__ float sm_qbase[EE];
    __shared__ unsigned char sm_mask[NPAD];
    __shared__ int   sm_cbase[32];
    __shared__ int   sm_newM;

    if (t < EE) sm_qbase[t] = g_qbase[b * EE + t];
    sm_blk[t]  = g_blk[b * NPAD + t];
    sm_idx[t]  = t;
    sm_mask[t] = (t == 0 || t >= NTOK) ? 1 : 0;

    {
        const uint4* src = (const uint4*)(g_V4u + ((size_t)b * 32 + warp) * NPAD);
        uint4* dst = (uint4*)(v_s + warp * NPAD);
        for (int i = lane; i < NPAD / 4; i += 32) dst[i] = src[i];
    }
    __syncthreads();

    const uint4* kq = g_K16 + (size_t)b * 8 * NPAD + t;
    const uint4* gq = g_G16 + (size_t)b * 8 * NPAD + t;
    int   cur   = 0;
    float total = 0.f;
    int   M_pad = NPAD;
    int   nch   = NPAD / 32;

    #pragma unroll 1
    for (int step = 0; step < NTOK - 1; ++step) {
        // ---- q row (as halves) ----
        if (t < EE)
            sm_qh[t] = __float2half(sm_qbase[t] + g_SK[((size_t)b * NTOK + cur) * EE + t]);
        __syncthreads();   // S1

        // ---- C: scores; 2 batches of 4 LDG.128 each ----
        const bool msk = sm_mask[t];
        if (t < M_pad) {
            uint4 r[4];
            #pragma unroll
            for (int g2 = 0; g2 < 2; ++g2) {
                #pragma unroll
                for (int i = 0; i < 4; ++i)
                    r[i] = kq[(size_t)(g2 * 4 + i) * NPAD];
                #pragma unroll
                for (int i = 0; i < 4; ++i) {
                    const int h = g2 * 4 + i;
                    const float a = dot16_fp8(r[i], (const __half2*)(sm_qh + h * 16));
                    smp[h * NPAD + t] = msk ? 0.f : __expf(a * SC_C);
                }
            }
        }
        __syncthreads();   // S2

        // ---- D: ctx; warp w owns quad w; V in smem, 2 tokens/lane ----
        {
            const int h = warp >> 2;
            float a0 = 0.f, a1 = 0.f, a2 = 0.f, a3 = 0.f, ps = 0.f;
            const uint2*  vt2 = (const uint2*)(v_s + warp * NPAD);
            const float2* pp2 = (const float2*)(smp + h * NPAD);
            const int m2 = M_pad >> 1;
            #pragma unroll 4
            for (int n2 = lane; n2 < m2; n2 += 32) {
                const uint2  r  = vt2[n2];
                const float2 p2 = pp2[n2];
                const float2 fA0 = __half22float2(fp8x2_to_h2((unsigned short)r.x));
                const float2 fA1 = __half22float2(fp8x2_to_h2((unsigned short)(r.x >> 16)));
                const float2 fB0 = __half22float2(fp8x2_to_h2((unsigned short)r.y));
                const float2 fB1 = __half22float2(fp8x2_to_h2((unsigned short)(r.y >> 16)));
                ps += p2.x + p2.y;
                a0 += p2.x * fA0.x + p2.y * fB0.x;
                a1 += p2.x * fA0.y + p2.y * fB0.y;
                a2 += p2.x * fA1.x + p2.y * fB1.x;
                a3 += p2.x * fA1.y + p2.y * fB1.y;
            }
            #pragma unroll
            for (int o = 16; o > 0; o >>= 1) {
                a0 += __shfl_xor_sync(~0u, a0, o);
                a1 += __shfl_xor_sync(~0u, a1, o);
                a2 += __shfl_xor_sync(~0u, a2, o);
                a3 += __shfl_xor_sync(~0u, a3, o);
                ps += __shfl_xor_sync(~0u, ps, o);
            }
            if (lane == 0) {
                const float inv = 1.0f / (ps * FP8S);
                sm_ctxh[warp * 4 + 0] = __float2half(a0 * inv);
                sm_ctxh[warp * 4 + 1] = __float2half(a1 * inv);
                sm_ctxh[warp * 4 + 2] = __float2half(a2 * inv);
                sm_ctxh[warp * 4 + 3] = __float2half(a3 * inv);
            }
        }
        __syncthreads();   // S3

        // ---- F: logits; 2 batches of 4 LDG.128; fused argmax + sum exp ----
        {
            float mv = NEGV, s = 0.f;
            int   mi = t;
            if (t < M_pad) {
                float d = 0.f;
                uint4 r[4];
                #pragma unroll
                for (int g2 = 0; g2 < 2; ++g2) {
                    #pragma unroll
                    for (int i = 0; i < 4; ++i)
                        r[i] = gq[(size_t)(g2 * 4 + i) * NPAD];
                    #pragma unroll
                    for (int i = 0; i < 4; ++i) {
                        const int o8 = g2 * 4 + i;
                        d += dot16_fp8(r[i], (const __half2*)(sm_ctxh + o8 * 16));
                    }
                }
                const float a = sm_blk[t] + d * (1.0f / FP8S);
                if (!msk) {
                    mv = a;
                    s  = __expf(tanh_fast(a * SCALE) * 10.0f);
                }
                #pragma unroll
                for (int o = 16; o > 0; o >>= 1) {
                    const float ov = __shfl_xor_sync(~0u, mv, o);
                    const int   oi = __shfl_xor_sync(~0u, mi, o);
                    s += __shfl_xor_sync(~0u, s, o);
                    if (ov > mv || (ov == mv && oi < mi)) { mv = ov; mi = oi; }
                }
            }
            if (lane == 0) {
                sm_wred[warp * 9 + 0] = mv;
                sm_wred[warp * 9 + 1] = s;
                sm_iwred[warp] = mi;
            }
        }
        __syncthreads();   // S4

        // ---- final reduce, redundant in every warp ----
        {
            float mv = sm_wred[lane * 9 + 0];
            float s  = sm_wred[lane * 9 + 1];
            int   mi = sm_iwred[lane];
            #pragma unroll
            for (int o = 16; o > 0; o >>= 1) {
                const float ov = __shfl_xor_sync(~0u, mv, o);
                const int   oi = __shfl_xor_sync(~0u, mi, o);
                s += __shfl_xor_sync(~0u, s, o);
                if (ov > mv || (ov == mv && oi < mi)) { mv = ov; mi = oi; }
            }
            if (t == 0) {
                total += tanhf(mv * SCALE) * 10.0f - logf(s);
                sm_mask[mi] = 1;
            }
            cur = sm_idx[mi];
        }

        // ---- periodic stable compaction ----
        if (((step + 1) & 63) == 0) {
            __syncthreads();                 // CS1
            if (warp == 0) {
                int cnt = 0;
                if (lane < nch) {
                    const unsigned char* mp = sm_mask + lane * 32;
                    #pragma unroll
                    for (int j = 0; j < 32; ++j) cnt += (mp[j] == 0);
                }
                int inc = cnt;
                #pragma unroll
                for (int o = 1; o < 32; o <<= 1) {
                    const int v = __shfl_up_sync(~0u, inc, o);
                    if (lane >= o) inc += v;
                }
                if (lane < nch) sm_cbase[lane] = inc - cnt;
                if (lane == nch - 1) sm_newM = inc;
            }
            __syncthreads();                 // CS2
            {
                for (int rr = warp; rr < 48; rr += 32) {
                    if (rr < 16) {
                        uint4* row = (rr < 8 ? g_K16 + ((size_t)b * 8 + rr) * NPAD
                                             : g_G16 + ((size_t)b * 8 + rr - 8) * NPAD);
                        for (int c = 0; c < nch; ++c) {
                            const int n = c * 32 + lane;
                            const uint4 v = row[n];
                            const bool keep = (sm_mask[n] == 0);
                            const unsigned bal = __ballot_sync(~0u, keep);
                            if (keep)
                                row[sm_cbase[c] + __popc(bal & ((1u << lane) - 1))] = v;
                        }
                    } else {
                        unsigned* row = v_s + (rr - 16) * NPAD;
                        for (int c = 0; c < nch; ++c) {
                            const int n = c * 32 + lane;
                            const unsigned v = row[n];
                            const bool keep = (sm_mask[n] == 0);
                            const unsigned bal = __ballot_sync(~0u, keep);
                            if (keep)
                                row[sm_cbase[c] + __popc(bal & ((1u << lane) - 1))] = v;
                        }
                    }
                }
                if (warp == 0) {
                    for (int c = 0; c < nch; ++c) {
                        const int n = c * 32 + lane;
                        const float v = sm_blk[n];
                        const bool keep = (sm_mask[n] == 0);
                        const unsigned bal = __ballot_sync(~0u, keep);
                        if (keep)
                            sm_blk[sm_cbase[c] + __popc(bal & ((1u << lane) - 1))] = v;
                    }
                }
                if (warp == 1) {
                    for (int c = 0; c < nch; ++c) {
                        const int n = c * 32 + lane;
                        const int v = sm_idx[n];
                        const bool keep = (sm_mask[n] == 0);
                        const unsigned bal = __ballot_sync(~0u, keep);
                        if (keep)
                            sm_idx[sm_cbase[c] + __popc(bal & ((1u << lane) - 1))] = v;
                    }
                }
            }
            __syncthreads();                 // CS3
            const int M = sm_newM;
            M_pad = (M + 31) & ~31;
            nch   = M_pad >> 5;
            sm_mask[t] = (t >= M) ? 1 : 0;
        }
    }

    if (t == 0) out[b] = total;
}

// ---------------------------------------------------------------------------
extern "C" void kernel_launch(void* const* d_in, const int* in_sizes, int n_in,
                              void* d_out, int out_size) {
    const float* node  = (const float*)d_in[0];
    const float* graph = (const float*)d_in[1];
    const float* Wqkv  = (const float*)d_in[2];
    const float* bqkv  = (const float*)d_in[3];
    const float* Wfix  = (const float*)d_in[4];
    const float* bfix  = (const float*)d_in[5];
    const float* Wstep = (const float*)d_in[6];
    const float* bstep = (const float*)d_in[7];
    const float* Wmlp  = (const float*)d_in[8];
    const float* bmlp  = (const float*)d_in[9];
    float* out = (float*)d_out;

    cudaFuncSetAttribute(decode_loop,
                         cudaFuncAttributeMaxDynamicSharedMemorySize, VSMEM_BYTES);

    dim3 blk2(16, 16);
    qkv_gemm<<<dim3(6, 16, BB), blk2>>>(node, Wqkv, bqkv);
    sk_gemm <<<dim3(2, 16, BB), blk2>>>(node, Wstep);
    g_gemm  <<<dim3(2, 16, BB), blk2>>>(Wmlp);
    blk_kernel <<<BB, NPAD>>>(bmlp);
    qbase_kernel<<<BB, EE>>>(graph, node, Wfix, bfix, Wstep, bstep);
    decode_loop<<<BB, 1024, VSMEM_BYTES>>>(out);
}

// round 16
// speedup vs baseline: 1.3807x; 1.1477x over previous
#include <cuda_runtime.h>
#include <cuda_bf16.h>
#include <cuda_fp16.h>
#include <cuda_fp8.h>
#include <math.h>

#define BB   128
#define NTOK 1000
#define NPAD 1024
#define EE   128
#define HH   8
#define NEGV (-1000000000.0f)
#define SCALE 0.25f
#define FP8S 256.0f            // storage scale for e4m3
#define SC_C (0.25f / 256.0f)  // score scale incl. fp8 unscale
#define VSMEM_BYTES (32 * NPAD * 4)   // 128 KB

// K, G: 16-feature interleave: (b,e,n) -> fp8 byte ((b*8+(e>>4))*NPAD+n)*16+(e&15)
// V: 4-feature quads: (b,e,n) -> fp8 byte ((b*32+(e>>2))*NPAD+n)*4+(e&3)
__device__ uint4    g_K16[BB * 8 * NPAD];
__device__ uint4    g_G16[BB * 8 * NPAD];
__device__ unsigned g_V4u[BB * 32 * NPAD];
__device__ __nv_bfloat16 g_LKp[BB * EE * NPAD];
__device__ float g_SK   [(size_t)BB * NTOK * EE];
__device__ float g_qbase[BB * EE];
__device__ float g_blk  [BB * NPAD];

static __device__ __forceinline__ unsigned char to_fp8(float v) {
    return (unsigned char)__nv_cvt_float_to_fp8(v * FP8S, __NV_SATFINITE, __NV_E4M3);
}

// ---------------------------------------------------------------------------
__global__ void qkv_gemm(const float* __restrict__ node,
                         const float* __restrict__ W,
                         const float* __restrict__ bias) {
    __shared__ float As[16][64];
    __shared__ float Bs[16][64];
    const int b  = blockIdx.z;
    const int n0 = blockIdx.y * 64;
    const int e0 = blockIdx.x * 64;
    const int tx = threadIdx.x, ty = threadIdx.y;
    const int t  = ty * 16 + tx;
    const int an = t >> 2, ak = (t & 3) * 4;
    const int bk = t >> 4, be = (t & 15) * 4;

    float acc[4][4] = {};
    for (int k0 = 0; k0 < 128; k0 += 16) {
        float4 av;
        const int n = n0 + an;
        if (n < NTOK) av = *(const float4*)&node[((size_t)b * NTOK + n) * EE + k0 + ak];
        else          av = make_float4(0.f, 0.f, 0.f, 0.f);
        As[ak + 0][an] = av.x; As[ak + 1][an] = av.y;
        As[ak + 2][an] = av.z; As[ak + 3][an] = av.w;
        *(float4*)&Bs[bk][be] = *(const float4*)&W[(size_t)(k0 + bk) * 384 + e0 + be];
        __syncthreads();
        #pragma unroll
        for (int kk = 0; kk < 16; ++kk) {
            float ar[4], br[4];
            #pragma unroll
            for (int i = 0; i < 4; ++i) ar[i] = As[kk][ty * 4 + i];
            #pragma unroll
            for (int j = 0; j < 4; ++j) br[j] = Bs[kk][tx * 4 + j];
            #pragma unroll
            for (int i = 0; i < 4; ++i)
                #pragma unroll
                for (int j = 0; j < 4; ++j) acc[i][j] += ar[i] * br[j];
        }
        __syncthreads();
    }

    unsigned char* K = (unsigned char*)g_K16;
    unsigned char* V = (unsigned char*)g_V4u;
    #pragma unroll
    for (int i = 0; i < 4; ++i) {
        const int n = n0 + ty * 4 + i;
        if (n >= NTOK) continue;
        #pragma unroll
        for (int j = 0; j < 4; ++j) {
            const int e3 = e0 + tx * 4 + j;
            const float v = acc[i][j] + bias[e3];
            if (e3 < 128) {
                const int e = e3;
                K[((size_t)(b * 8 + (e >> 4)) * NPAD + n) * 16 + (e & 15)] = to_fp8(v);
            } else if (e3 < 256) {
                const int e = e3 - 128;
                V[((size_t)(b * 32 + (e >> 2)) * NPAD + n) * 4 + (e & 3)] = to_fp8(v);
            } else {
                const int e = e3 - 256;
                g_LKp[(size_t)(b * EE + e) * NPAD + n] = __float2bfloat16(v);
            }
        }
    }
}

// ---------------------------------------------------------------------------
__global__ void sk_gemm(const float* __restrict__ node,
                        const float* __restrict__ Wstep) {
    __shared__ float As[16][64];
    __shared__ float Bs[16][64];
    const float* W2 = Wstep + 128 * EE;
    const int b  = blockIdx.z;
    const int n0 = blockIdx.y * 64;
    const int e0 = blockIdx.x * 64;
    const int tx = threadIdx.x, ty = threadIdx.y;
    const int t  = ty * 16 + tx;
    const int an = t >> 2, ak = (t & 3) * 4;
    const int bk = t >> 4, be = (t & 15) * 4;

    float acc[4][4] = {};
    for (int k0 = 0; k0 < 128; k0 += 16) {
        float4 av;
        const int n = n0 + an;
        if (n < NTOK) av = *(const float4*)&node[((size_t)b * NTOK + n) * EE + k0 + ak];
        else          av = make_float4(0.f, 0.f, 0.f, 0.f);
        As[ak + 0][an] = av.x; As[ak + 1][an] = av.y;
        As[ak + 2][an] = av.z; As[ak + 3][an] = av.w;
        *(float4*)&Bs[bk][be] = *(const float4*)&W2[(size_t)(k0 + bk) * EE + e0 + be];
        __syncthreads();
        #pragma unroll
        for (int kk = 0; kk < 16; ++kk) {
            float ar[4], br[4];
            #pragma unroll
            for (int i = 0; i < 4; ++i) ar[i] = As[kk][ty * 4 + i];
            #pragma unroll
            for (int j = 0; j < 4; ++j) br[j] = Bs[kk][tx * 4 + j];
            #pragma unroll
            for (int i = 0; i < 4; ++i)
                #pragma unroll
                for (int j = 0; j < 4; ++j) acc[i][j] += ar[i] * br[j];
        }
        __syncthreads();
    }
    #pragma unroll
    for (int i = 0; i < 4; ++i) {
        const int n = n0 + ty * 4 + i;
        if (n >= NTOK) continue;
        #pragma unroll
        for (int j = 0; j < 4; ++j)
            g_SK[((size_t)b * NTOK + n) * EE + e0 + tx * 4 + j] = acc[i][j];
    }
}

// ---------------------------------------------------------------------------
__global__ void g_gemm(const float* __restrict__ Wmlp) {
    __shared__ float As[16][64];
    __shared__ float Bs[16][64];
    const int b  = blockIdx.z;
    const int n0 = blockIdx.y * 64;
    const int c0 = blockIdx.x * 64;
    const int tx = threadIdx.x, ty = threadIdx.y;
    const int t  = ty * 16 + tx;
    const int ac = t >> 2, ae = (t & 3) * 4;
    const int bk = t >> 4, bn = (t & 15) * 4;

    float acc[4][4] = {};
    for (int k0 = 0; k0 < 128; k0 += 16) {
        const float4 av = *(const float4*)&Wmlp[(size_t)(c0 + ac) * EE + k0 + ae];
        As[ae + 0][ac] = av.x; As[ae + 1][ac] = av.y;
        As[ae + 2][ac] = av.z; As[ae + 3][ac] = av.w;
        const uint2 r = *(const uint2*)&g_LKp[(size_t)(b * EE + k0 + bk) * NPAD + n0 + bn];
        const float2 v0 = __bfloat1622float2(*(const __nv_bfloat162*)&r.x);
        const float2 v1 = __bfloat1622float2(*(const __nv_bfloat162*)&r.y);
        Bs[bk][bn + 0] = v0.x; Bs[bk][bn + 1] = v0.y;
        Bs[bk][bn + 2] = v1.x; Bs[bk][bn + 3] = v1.y;
        __syncthreads();
        #pragma unroll
        for (int kk = 0; kk < 16; ++kk) {
            float ar[4], br[4];
            #pragma unroll
            for (int i = 0; i < 4; ++i) ar[i] = As[kk][ty * 4 + i];
            #pragma unroll
            for (int j = 0; j < 4; ++j) br[j] = Bs[kk][tx * 4 + j];
            #pragma unroll
            for (int i = 0; i < 4; ++i)
                #pragma unroll
                for (int j = 0; j < 4; ++j) acc[i][j] += ar[i] * br[j];
        }
        __syncthreads();
    }
    unsigned char* G = (unsigned char*)g_G16;
    #pragma unroll
    for (int i = 0; i < 4; ++i) {
        const int c = c0 + ty * 4 + i;
        #pragma unroll
        for (int j = 0; j < 4; ++j) {
            const int n = n0 + tx * 4 + j;
            G[((size_t)(b * 8 + (c >> 4)) * NPAD + n) * 16 + (c & 15)] = to_fp8(acc[i][j]);
        }
    }
}

// ---------------------------------------------------------------------------
__global__ void blk_kernel(const float* __restrict__ bmlp) {
    const int b = blockIdx.x, n = threadIdx.x;
    __shared__ float bm[EE];
    if (n < EE) bm[n] = bmlp[n];
    __syncthreads();
    float a = 0.f;
    #pragma unroll 8
    for (int e = 0; e < EE; ++e)
        a += bm[e] * __bfloat162float(g_LKp[(size_t)(b * EE + e) * NPAD + n]);
    g_blk[b * NPAD + n] = a;
}

// ---------------------------------------------------------------------------
__global__ void qbase_kernel(const float* __restrict__ g,
                             const float* __restrict__ node,
                             const float* __restrict__ Wfix,
                             const float* __restrict__ bfix,
                             const float* __restrict__ Wstep,
                             const float* __restrict__ bstep) {
    const int b = blockIdx.x, e = threadIdx.x;
    __shared__ float gs[EE], fs[EE];
    gs[e] = g[b * EE + e];
    fs[e] = node[(size_t)b * NTOK * EE + e];
    __syncthreads();
    float a = bfix[e] + bstep[e];
    #pragma unroll 4
    for (int k = 0; k < EE; ++k) {
        a += gs[k] * Wfix[(size_t)k * EE + e];
        a += fs[k] * Wstep[(size_t)k * EE + e];
    }
    g_qbase[b * EE + e] = a;
}

__device__ __forceinline__ float tanh_fast(float x) {
    float r;
    asm("tanh.approx.f32 %0, %1;" : "=f"(r) : "f"(x));
    return r;
}

__device__ __forceinline__ __half2 fp8x2_to_h2(unsigned short v) {
    __half2 h;
    asm("cvt.rn.f16x2.e4m3x2 %0, %1;" : "=r"(*(unsigned*)&h) : "h"(v));
    return h;
}

__device__ __forceinline__ __half2 h2shfl_xor(__half2 v, int o) {
    unsigned u = *(unsigned*)&v;
    u = __shfl_xor_sync(~0u, u, o);
    return *(__half2*)&u;
}

// 16 e4m3 (uint4) dot 16 halves -> float (used in C, needs per-head scalar)
__device__ __forceinline__ float dot16_fp8(const uint4 r, const __half2* __restrict__ qh) {
    __half2 acc = __float2half2_rn(0.f);
    acc = __hfma2(fp8x2_to_h2((unsigned short)(r.x)),       qh[0], acc);
    acc = __hfma2(fp8x2_to_h2((unsigned short)(r.x >> 16)), qh[1], acc);
    acc = __hfma2(fp8x2_to_h2((unsigned short)(r.y)),       qh[2], acc);
    acc = __hfma2(fp8x2_to_h2((unsigned short)(r.y >> 16)), qh[3], acc);
    acc = __hfma2(fp8x2_to_h2((unsigned short)(r.z)),       qh[4], acc);
    acc = __hfma2(fp8x2_to_h2((unsigned short)(r.z >> 16)), qh[5], acc);
    acc = __hfma2(fp8x2_to_h2((unsigned short)(r.w)),       qh[6], acc);
    acc = __hfma2(fp8x2_to_h2((unsigned short)(r.w >> 16)), qh[7], acc);
    return __low2float(acc) + __high2float(acc);
}

// accumulating variant for F (one convert at the very end)
__device__ __forceinline__ __half2 dot16_fp8_acc(const uint4 r,
                                                 const __half2* __restrict__ qh,
                                                 __half2 acc) {
    acc = __hfma2(fp8x2_to_h2((unsigned short)(r.x)),       qh[0], acc);
    acc = __hfma2(fp8x2_to_h2((unsigned short)(r.x >> 16)), qh[1], acc);
    acc = __hfma2(fp8x2_to_h2((unsigned short)(r.y)),       qh[2], acc);
    acc = __hfma2(fp8x2_to_h2((unsigned short)(r.y >> 16)), qh[3], acc);
    acc = __hfma2(fp8x2_to_h2((unsigned short)(r.z)),       qh[4], acc);
    acc = __hfma2(fp8x2_to_h2((unsigned short)(r.z >> 16)), qh[5], acc);
    acc = __hfma2(fp8x2_to_h2((unsigned short)(r.w)),       qh[6], acc);
    acc = __hfma2(fp8x2_to_h2((unsigned short)(r.w >> 16)), qh[7], acc);
    return acc;
}

// ---------------------------------------------------------------------------
// Persistent decode loop; smp in half; phase D in half2 HFMA2.
// ---------------------------------------------------------------------------
__global__ void __launch_bounds__(1024, 1)
decode_loop(float* __restrict__ out) {
    const int b    = blockIdx.x;
    const int t    = threadIdx.x;
    const int warp = t >> 5, lane = t & 31;

    extern __shared__ unsigned v_s[];                // 128 KB V

    __shared__ __align__(16) __half smp[HH * NPAD];  // 16 KB (half!)
    __shared__ float sm_blk[NPAD];
    __shared__ int   sm_idx[NPAD];
    __shared__ float sm_wred[32 * 9];
    __shared__ int   sm_iwred[32];
    __shared__ __align__(16) __half sm_qh[EE];
    __shared__ __align__(16) __half sm_ctxh[EE];
    __shared__ float sm_qbase[EE];
    __shared__ unsigned char sm_mask[NPAD];
    __shared__ int   sm_cbase[32];
    __shared__ int   sm_newM;

    if (t < EE) sm_qbase[t] = g_qbase[b * EE + t];
    sm_blk[t]  = g_blk[b * NPAD + t];
    sm_idx[t]  = t;
    sm_mask[t] = (t == 0 || t >= NTOK) ? 1 : 0;

    {
        const uint4* src = (const uint4*)(g_V4u + ((size_t)b * 32 + warp) * NPAD);
        uint4* dst = (uint4*)(v_s + warp * NPAD);
        for (int i = lane; i < NPAD / 4; i += 32) dst[i] = src[i];
    }
    __syncthreads();

    const uint4* kq = g_K16 + (size_t)b * 8 * NPAD + t;
    const uint4* gq = g_G16 + (size_t)b * 8 * NPAD + t;
    int   cur   = 0;
    float total = 0.f;
    int   M_pad = NPAD;
    int   nch   = NPAD / 32;

    #pragma unroll 1
    for (int step = 0; step < NTOK - 1; ++step) {
        // ---- q row (as halves) ----
        if (t < EE)
            sm_qh[t] = __float2half(sm_qbase[t] + g_SK[((size_t)b * NTOK + cur) * EE + t]);
        __syncthreads();   // S1

        // ---- C: scores; store p as half ----
        const bool msk = sm_mask[t];
        if (t < M_pad) {
            #pragma unroll
            for (int h = 0; h < HH; ++h) {
                const float a = dot16_fp8(kq[(size_t)h * NPAD],
                                          (const __half2*)(sm_qh + h * 16));
                smp[h * NPAD + t] = __float2half(msk ? 0.f : __expf(a * SC_C));
            }
        }
        __syncthreads();   // S2

        // ---- D: ctx; warp w owns quad w; V+p in smem, half2 HFMA2, 2 tok/lane ----
        {
            const int h = warp >> 2;
            const __half2 hz = __float2half2_rn(0.f);
            __half2 acc01 = hz, acc23 = hz, ps2 = hz;
            const uint2*   vt2 = (const uint2*)(v_s + warp * NPAD);
            const __half2* pp2 = (const __half2*)(smp + h * NPAD);
            const int m2 = M_pad >> 1;
            #pragma unroll 4
            for (int n2 = lane; n2 < m2; n2 += 32) {
                const uint2   r  = vt2[n2];          // tokens 2*n2, 2*n2+1 (4 features each)
                const __half2 p2 = pp2[n2];          // (pA, pB)
                const __half2 pA = __low2half2(p2);
                const __half2 pB = __high2half2(p2);
                acc01 = __hfma2(pA, fp8x2_to_h2((unsigned short)r.x),         acc01);
                acc23 = __hfma2(pA, fp8x2_to_h2((unsigned short)(r.x >> 16)), acc23);
                acc01 = __hfma2(pB, fp8x2_to_h2((unsigned short)r.y),         acc01);
                acc23 = __hfma2(pB, fp8x2_to_h2((unsigned short)(r.y >> 16)), acc23);
                ps2   = __hadd2(ps2, p2);
            }
            #pragma unroll
            for (int o = 16; o > 0; o >>= 1) {
                acc01 = __hadd2(acc01, h2shfl_xor(acc01, o));
                acc23 = __hadd2(acc23, h2shfl_xor(acc23, o));
                ps2   = __hadd2(ps2,   h2shfl_xor(ps2, o));
            }
            if (lane == 0) {
                const float ps = __low2float(ps2) + __high2float(ps2);
                const float inv = 1.0f / (ps * FP8S);
                sm_ctxh[warp * 4 + 0] = __float2half(__low2float(acc01)  * inv);
                sm_ctxh[warp * 4 + 1] = __float2half(__high2float(acc01) * inv);
                sm_ctxh[warp * 4 + 2] = __float2half(__low2float(acc23)  * inv);
                sm_ctxh[warp * 4 + 3] = __float2half(__high2float(acc23) * inv);
            }
        }
        __syncthreads();   // S3

        // ---- F: logits; half2 accumulation across all 8 dots ----
        {
            float mv = NEGV, s = 0.f;
            int   mi = t;
            if (t < M_pad) {
                __half2 dacc = __float2half2_rn(0.f);
                #pragma unroll
                for (int o8 = 0; o8 < 8; ++o8)
                    dacc = dot16_fp8_acc(gq[(size_t)o8 * NPAD],
                                         (const __half2*)(sm_ctxh + o8 * 16), dacc);
                const float d = __low2float(dacc) + __high2float(dacc);
                const float a = sm_blk[t] + d * (1.0f / FP8S);
                if (!msk) {
                    mv = a;
                    s  = __expf(tanh_fast(a * SCALE) * 10.0f);
                }
                #pragma unroll
                for (int o = 16; o > 0; o >>= 1) {
                    const float ov = __shfl_xor_sync(~0u, mv, o);
                    const int   oi = __shfl_xor_sync(~0u, mi, o);
                    s += __shfl_xor_sync(~0u, s, o);
                    if (ov > mv || (ov == mv && oi < mi)) { mv = ov; mi = oi; }
                }
            }
            if (lane == 0) {
                sm_wred[warp * 9 + 0] = mv;
                sm_wred[warp * 9 + 1] = s;
                sm_iwred[warp] = mi;
            }
        }
        __syncthreads();   // S4

        // ---- final reduce, redundant in every warp ----
        {
            float mv = sm_wred[lane * 9 + 0];
            float s  = sm_wred[lane * 9 + 1];
            int   mi = sm_iwred[lane];
            #pragma unroll
            for (int o = 16; o > 0; o >>= 1) {
                const float ov = __shfl_xor_sync(~0u, mv, o);
                const int   oi = __shfl_xor_sync(~0u, mi, o);
                s += __shfl_xor_sync(~0u, s, o);
                if (ov > mv || (ov == mv && oi < mi)) { mv = ov; mi = oi; }
            }
            if (t == 0) {
                total += tanhf(mv * SCALE) * 10.0f - logf(s);
                sm_mask[mi] = 1;
            }
            cur = sm_idx[mi];
        }

        // ---- periodic stable compaction ----
        if (((step + 1) & 63) == 0) {
            __syncthreads();                 // CS1
            if (warp == 0) {
                int cnt = 0;
                if (lane < nch) {
                    const unsigned char* mp = sm_mask + lane * 32;
                    #pragma unroll
                    for (int j = 0; j < 32; ++j) cnt += (mp[j] == 0);
                }
                int inc = cnt;
                #pragma unroll
                for (int o = 1; o < 32; o <<= 1) {
                    const int v = __shfl_up_sync(~0u, inc, o);
                    if (lane >= o) inc += v;
                }
                if (lane < nch) sm_cbase[lane] = inc - cnt;
                if (lane == nch - 1) sm_newM = inc;
            }
            __syncthreads();                 // CS2
            {
                for (int rr = warp; rr < 48; rr += 32) {
                    if (rr < 16) {
                        uint4* row = (rr < 8 ? g_K16 + ((size_t)b * 8 + rr) * NPAD
                                             : g_G16 + ((size_t)b * 8 + rr - 8) * NPAD);
                        for (int c = 0; c < nch; ++c) {
                            const int n = c * 32 + lane;
                            const uint4 v = row[n];
                            const bool keep = (sm_mask[n] == 0);
                            const unsigned bal = __ballot_sync(~0u, keep);
                            if (keep)
                                row[sm_cbase[c] + __popc(bal & ((1u << lane) - 1))] = v;
                        }
                    } else {
                        unsigned* row = v_s + (rr - 16) * NPAD;
                        for (int c = 0; c < nch; ++c) {
                            const int n = c * 32 + lane;
                            const unsigned v = row[n];
                            const bool keep = (sm_mask[n] == 0);
                            const unsigned bal = __ballot_sync(~0u, keep);
                            if (keep)
                                row[sm_cbase[c] + __popc(bal & ((1u << lane) - 1))] = v;
                        }
                    }
                }
                if (warp == 0) {
                    for (int c = 0; c < nch; ++c) {
                        const int n = c * 32 + lane;
                        const float v = sm_blk[n];
                        const bool keep = (sm_mask[n] == 0);
                        const unsigned bal = __ballot_sync(~0u, keep);
                        if (keep)
                            sm_blk[sm_cbase[c] + __popc(bal & ((1u << lane) - 1))] = v;
                    }
                }
                if (warp == 1) {
                    for (int c = 0; c < nch; ++c) {
                        const int n = c * 32 + lane;
                        const int v = sm_idx[n];
                        const bool keep = (sm_mask[n] == 0);
                        const unsigned bal = __ballot_sync(~0u, keep);
                        if (keep)
                            sm_idx[sm_cbase[c] + __popc(bal & ((1u << lane) - 1))] = v;
                    }
                }
            }
            __syncthreads();                 // CS3
            const int M = sm_newM;
            M_pad = (M + 31) & ~31;
            nch   = M_pad >> 5;
            sm_mask[t] = (t >= M) ? 1 : 0;
        }
    }

    if (t == 0) out[b] = total;
}

// ---------------------------------------------------------------------------
extern "C" void kernel_launch(void* const* d_in, const int* in_sizes, int n_in,
                              void* d_out, int out_size) {
    const float* node  = (const float*)d_in[0];
    const float* graph = (const float*)d_in[1];
    const float* Wqkv  = (const float*)d_in[2];
    const float* bqkv  = (const float*)d_in[3];
    const float* Wfix  = (const float*)d_in[4];
    const float* bfix  = (const float*)d_in[5];
    const float* Wstep = (const float*)d_in[6];
    const float* bstep = (const float*)d_in[7];
    const float* Wmlp  = (const float*)d_in[8];
    const float* bmlp  = (const float*)d_in[9];
    float* out = (float*)d_out;

    cudaFuncSetAttribute(decode_loop,
                         cudaFuncAttributeMaxDynamicSharedMemorySize, VSMEM_BYTES);

    dim3 blk2(16, 16);
    qkv_gemm<<<dim3(6, 16, BB), blk2>>>(node, Wqkv, bqkv);
    sk_gemm <<<dim3(2, 16, BB), blk2>>>(node, Wstep);
    g_gemm  <<<dim3(2, 16, BB), blk2>>>(Wmlp);
    blk_kernel <<<BB, NPAD>>>(bmlp);
    qbase_kernel<<<BB, EE>>>(graph, node, Wfix, bfix, Wstep, bstep);
    decode_loop<<<BB, 1024, VSMEM_BYTES>>>(out);
}